// round 9
// baseline (speedup 1.0000x reference)
#include <cuda_runtime.h>
#include <cuda_bf16.h>

// Problem constants (fixed by reference setup_inputs)
#define HH   1024
#define WW   1024
#define NC   8
#define NCOL (WW * NC)      // 8192 flat columns in [y][x][c] layout
#define NSEG 32
#define SEGH (HH / NSEG)    // 32
#define NPOOL 7

// Scratch: SAT in channel-last layout [y][x][c], fp32. 32 MB (fits L2).
__device__ float g_sat[(size_t)HH * NCOL];
// Decoupled-lookback links per (seg, flat col):
//   {float_bits:32 | flags} flags: bit0 = aggregate ready, bit1 = inclusive.
__device__ unsigned long long g_link[NSEG * NCOL];   // 2 MB

// ---------------------------------------------------------------------------
// Pass 1: inclusive row scan, barrier-free after init. Block = 1 row, 8
// autonomous warps; warp w owns x in [128w, 128w+128), all 8 channels
// (4 x / lane). Cross-warp row offsets via smem aggregate publish + spin
// (no __syncthreads on the hot path). Staging: per-warp 256 float4 chunks,
// chunk k = 2*x_local + half, XOR-swizzled ks = k ^ (lane&7) -> 16B-aligned
// AND bank-conflict-free on both STS.128 and LDS.128. Drain is coalesced
// STG.128. Also resets colscan's lookback links.
// ---------------------------------------------------------------------------
__global__ void __launch_bounds__(256) rowscan_kernel(const float* __restrict__ in) {
    __shared__ float stage[8 * 1024];      // 32 KB (8 warps x 256 float4)
    __shared__ float agg[8 * 8];           // per-warp per-channel aggregates
    __shared__ int   flag[8];

    const int y = blockIdx.x;
    const int t = threadIdx.x;
    const int l = t & 31;
    const int w = t >> 5;

    // Reset colscan lookback links (256 entries per row).
    g_link[(size_t)y * 256 + t] = 0ull;

    if (l == 0) flag[w] = 0;
    __syncthreads();     // the only block barrier (cheap, pre-load)

    // ---- load 4 consecutive x per channel, sequential in-register prefix --
    float4 v[NC];
    #pragma unroll
    for (int c = 0; c < NC; ++c) {
        v[c] = ((const float4*)(in + (size_t)c * (HH * WW) + (size_t)y * WW + w * 128))[l];
        v[c].y += v[c].x; v[c].z += v[c].y; v[c].w += v[c].z;
    }

    // ---- warp inclusive scan of per-thread totals (8 channels, ILP) ------
    float excl[NC];
    #pragma unroll
    for (int c = 0; c < NC; ++c) {
        float s = v[c].w;
        #pragma unroll
        for (int d = 1; d < 32; d <<= 1) {
            float nb = __shfl_up_sync(0xffffffffu, s, d);
            if (l >= d) s += nb;
        }
        excl[c] = s - v[c].w;
        if (l == 31) agg[w * 8 + c] = s;   // segment aggregate
    }

    // ---- publish aggregates (release: syncwarp -> fence -> flag) ----------
    __syncwarp();
    __threadfence_block();
    if (l == 0) atomicExch(&flag[w], 1);

    // ---- stage raw + intra-warp offsets, swizzled chunks ------------------
    float* reg = stage + w * 1024;
    const int kb = 8 * l;          // base chunk for this lane
    const int sw = l & 7;          // XOR swizzle key
    #pragma unroll
    for (int i = 0; i < 4; ++i) {
        const float* e = excl;
        float4 a, b;
        if (i == 0) { a = make_float4(v[0].x+e[0], v[1].x+e[1], v[2].x+e[2], v[3].x+e[3]);
                      b = make_float4(v[4].x+e[4], v[5].x+e[5], v[6].x+e[6], v[7].x+e[7]); }
        if (i == 1) { a = make_float4(v[0].y+e[0], v[1].y+e[1], v[2].y+e[2], v[3].y+e[3]);
                      b = make_float4(v[4].y+e[4], v[5].y+e[5], v[6].y+e[6], v[7].y+e[7]); }
        if (i == 2) { a = make_float4(v[0].z+e[0], v[1].z+e[1], v[2].z+e[2], v[3].z+e[3]);
                      b = make_float4(v[4].z+e[4], v[5].z+e[5], v[6].z+e[6], v[7].z+e[7]); }
        if (i == 3) { a = make_float4(v[0].w+e[0], v[1].w+e[1], v[2].w+e[2], v[3].w+e[3]);
                      b = make_float4(v[4].w+e[4], v[5].w+e[5], v[6].w+e[6], v[7].w+e[7]); }
        *(float4*)&reg[(kb + ((2 * i)     ^ sw)) * 4] = a;
        *(float4*)&reg[(kb + ((2 * i + 1) ^ sw)) * 4] = b;
    }

    // ---- lookback: sum aggregates of preceding segments -------------------
    float4 off03 = make_float4(0.f, 0.f, 0.f, 0.f);
    float4 off47 = off03;
    for (int p = 0; p < w; ++p)
        while (((volatile int*)flag)[p] == 0) { }
    __threadfence_block();
    for (int p = 0; p < w; ++p) {
        float4 a = *(float4*)&agg[p * 8];
        float4 b = *(float4*)&agg[p * 8 + 4];
        off03.x += a.x; off03.y += a.y; off03.z += a.z; off03.w += a.w;
        off47.x += b.x; off47.y += b.y; off47.z += b.z; off47.w += b.w;
    }

    __syncwarp();   // staging (cross-lane) complete before drain reads

    // ---- drain: coalesced stores, lane parity selects channel half --------
    const float4 myoff = (l & 1) ? off47 : off03;
    float4* out4 = (float4*)(g_sat + (size_t)y * NCOL) + w * 256;
    #pragma unroll
    for (int j = 0; j < 8; ++j) {
        const int F  = 32 * j + l;
        const int ks = F ^ ((F >> 3) & 7);
        float4 val = *(float4*)&reg[ks * 4];
        val.x += myoff.x; val.y += myoff.y; val.z += myoff.z; val.w += myoff.w;
        out4[F] = val;
    }
}

// ---------------------------------------------------------------------------
// Pass 2: single-pass column cumsum, decoupled lookback with early aggregate
// publish (no serial cross-segment chain). Block = 1 segment (32 rows) x 256
// columns; seg ascends with blockIdx (deps point to lower bids -> no deadlock).
// ---------------------------------------------------------------------------
__global__ void __launch_bounds__(256) colscan_kernel() {
    const int tid   = threadIdx.x;
    const int seg   = blockIdx.x >> 5;       // NCOL/256 = 32 chunks per seg
    const int chunk = blockIdx.x & 31;
    const int f     = chunk * 256 + tid;

    float* base = g_sat + (size_t)seg * SEGH * NCOL + f;

    // Local inclusive prefix over the 32 segment rows (reg-resident).
    float pref[SEGH];
    float s = 0.f;
    #pragma unroll
    for (int k = 0; k < SEGH; ++k) {
        s += __ldcg(base + (size_t)k * NCOL);
        pref[k] = s;
    }

    // Publish local aggregate immediately (flag = 1).
    if (seg < NSEG - 1) {
        unsigned long long agg =
            ((unsigned long long)__float_as_uint(s) << 32) | 1ull;
        atomicExch(&g_link[(size_t)seg * NCOL + f], agg);
    }

    // Lookback: walk predecessors, summing aggregates, stop at an inclusive.
    float off = 0.f;
    for (int i = seg - 1; i >= 0; --i) {
        unsigned long long u;
        do {
            u = atomicAdd(&g_link[(size_t)i * NCOL + f], 0ull);
        } while (!(u & 1ull));
        off += __uint_as_float((unsigned)(u >> 32));
        if (u & 2ull) break;       // that value was inclusive -> done
    }

    // Publish inclusive prefix (flag = 3).
    if (seg < NSEG - 1) {
        unsigned long long inc =
            ((unsigned long long)__float_as_uint(off + s) << 32) | 3ull;
        atomicExch(&g_link[(size_t)seg * NCOL + f], inc);
    }

    // Finalize in place.
    #pragma unroll
    for (int k = 0; k < SEGH; ++k)
        __stcg(base + (size_t)k * NCOL, pref[k] + off);
}

// ---------------------------------------------------------------------------
// Pass 3: adaptive 7x7 ROI pooling + final mean. One warp per ROI.
// g_sat holds inclusive SAT; padded sat(y,x) = g_sat[y-1][x-1] (0 at borders).
// ---------------------------------------------------------------------------
__device__ __forceinline__ void load8(int y, int x, float v[8]) {
    if (y > 0 && x > 0) {
        const float4* p = (const float4*)(g_sat + ((size_t)(y - 1) * WW + (x - 1)) * NC);
        float4 a = p[0], b = p[1];
        v[0] = a.x; v[1] = a.y; v[2] = a.z; v[3] = a.w;
        v[4] = b.x; v[5] = b.y; v[6] = b.z; v[7] = b.w;
    } else {
        #pragma unroll
        for (int c = 0; c < 8; ++c) v[c] = 0.f;
    }
}

__global__ void __launch_bounds__(256) pool_kernel(const int* __restrict__ rois,
                                                   float* __restrict__ out, int n) {
    const int warp = (blockIdx.x * blockDim.x + threadIdx.x) >> 5;
    const int lane = threadIdx.x & 31;
    if (warp >= n) return;

    // rois is int32 [n,4]
    const int4 R = ((const int4*)rois)[warp];
    const int ymin = R.x >> 5;            // // FEAT_STRIDE (=32)
    const int xmin = R.y >> 5;
    const int ymax = (R.z >> 5) + 1;      // exclusive
    const int xmax = (R.w >> 5) + 1;
    const int leny = ymax - ymin;
    const int lenx = xmax - xmin;

    float acc[8];
    #pragma unroll
    for (int c = 0; c < 8; ++c) acc[c] = 0.f;

    for (int bin = lane; bin < 49; bin += 32) {
        const int i = bin / 7;
        const int j = bin - i * 7;
        const int ylo = ymin + (i * leny) / NPOOL;
        const int yhi = ymin + ((i + 1) * leny + NPOOL - 1) / NPOOL;
        const int xlo = xmin + (j * lenx) / NPOOL;
        const int xhi = xmin + ((j + 1) * lenx + NPOOL - 1) / NPOOL;

        float Shh[8], Slh[8], Shl[8], Sll[8];
        load8(yhi, xhi, Shh);
        load8(ylo, xhi, Slh);
        load8(yhi, xlo, Shl);
        load8(ylo, xlo, Sll);

        const int   area = (yhi - ylo) * (xhi - xlo);
        const float w    = 1.f / (float)area;
        #pragma unroll
        for (int c = 0; c < 8; ++c)
            acc[c] += w * ((Shh[c] - Slh[c]) - (Shl[c] - Sll[c]));
    }

    #pragma unroll
    for (int c = 0; c < 8; ++c) {
        #pragma unroll
        for (int d = 16; d; d >>= 1)
            acc[c] += __shfl_xor_sync(0xffffffffu, acc[c], d);
    }

    if (lane == 0) {
        const float inv49 = 1.f / 49.f;
        float4 o0 = make_float4(acc[0] * inv49, acc[1] * inv49, acc[2] * inv49, acc[3] * inv49);
        float4 o1 = make_float4(acc[4] * inv49, acc[5] * inv49, acc[6] * inv49, acc[7] * inv49);
        float4* o = (float4*)(out + (size_t)warp * 8);
        o[0] = o0;
        o[1] = o1;
    }
}

// ---------------------------------------------------------------------------
extern "C" void kernel_launch(void* const* d_in, const int* in_sizes, int n_in,
                              void* d_out, int out_size) {
    const float* conv = (const float*)d_in[0];   // [8,1024,1024] fp32
    const int*   rois = (const int*)d_in[1];     // [n,4] int32
    float*       out  = (float*)d_out;           // [n,8] fp32
    const int n = in_sizes[1] / 4;

    rowscan_kernel<<<HH, 256>>>(conv);
    colscan_kernel<<<NSEG * (NCOL / 256), 256>>>();
    pool_kernel   <<<(n + 7) / 8, 256>>>(rois, out, n);
}

// round 10
// speedup vs baseline: 1.4710x; 1.4710x over previous
#include <cuda_runtime.h>
#include <cuda_bf16.h>

// Problem constants (fixed by reference setup_inputs)
#define HH   1024
#define WW   1024
#define NC   8
#define NCOL (WW * NC)      // 8192 flat columns in [y][x][c] layout
#define NSEG 32
#define SEGH (HH / NSEG)    // 32
#define NPOOL 7

// Scratch: SAT in channel-last layout [y][x][c], fp32. 32 MB (fits L2).
__device__ float g_sat[(size_t)HH * NCOL];
// Decoupled-lookback links per (seg, flat col):
//   {float_bits:32 | flags} flags: bit0 = aggregate ready, bit1 = inclusive.
__device__ unsigned long long g_link[NSEG * NCOL];   // 2 MB

// ---------------------------------------------------------------------------
// Pass 1: inclusive row scan (along x), 4 elements per thread (float4),
// register-sequential prefix + warp scan of totals + 8-warp block combine.
// Transpose to channel-last layout via padded smem for coalesced stores.
// One block (256 threads) per row y. Also resets lookback links (256/row).
// [Best-measured rowscan: 14.18 us]
// ---------------------------------------------------------------------------
__global__ void __launch_bounds__(256) rowscan_kernel(const float* __restrict__ in) {
    __shared__ float wsum[NC][8];
    __shared__ float sbuf[256 * 33];      // padded transpose buffer (33 KB)

    const int y    = blockIdx.x;
    const int t    = threadIdx.x;
    const int lane = t & 31;
    const int wid  = t >> 5;

    // Reset lookback links: NSEG*NCOL = 262144 entries / 1024 rows = 256 each.
    g_link[(size_t)y * 256 + t] = 0ull;

    // Load 4 consecutive x per channel; sequential in-register prefix.
    float4 v[NC];
    float  tot[NC], excl[NC];
    #pragma unroll
    for (int c = 0; c < NC; ++c) {
        v[c] = ((const float4*)(in + (size_t)c * (HH * WW) + (size_t)y * WW))[t];
        v[c].y += v[c].x;
        v[c].z += v[c].y;
        v[c].w += v[c].z;
        tot[c] = v[c].w;
    }

    // Warp inclusive scan of per-thread totals; derive exclusive offset.
    #pragma unroll
    for (int c = 0; c < NC; ++c) {
        float s = tot[c];
        #pragma unroll
        for (int d = 1; d < 32; d <<= 1) {
            float nb = __shfl_up_sync(0xffffffffu, s, d);
            if (lane >= d) s += nb;
        }
        excl[c] = s - tot[c];
        if (lane == 31) wsum[c][wid] = s;
    }
    __syncthreads();

    // Warp 0 scans the 8 warp totals per channel (width-8 groups).
    if (wid == 0) {
        #pragma unroll
        for (int c = 0; c < NC; ++c) {
            float w = (lane < 8) ? wsum[c][lane] : 0.f;
            #pragma unroll
            for (int d = 1; d < 8; d <<= 1) {
                float nb = __shfl_up_sync(0xffffffffu, w, d);
                if ((lane & 7) >= d) w += nb;
            }
            if (lane < 8) wsum[c][lane] = w;
        }
    }
    __syncthreads();

    // Final values -> padded smem in [x][c] order: idx = 33*t + 8*i + c.
    // (write banks = lane + const : conflict-free)
    #pragma unroll
    for (int c = 0; c < NC; ++c) {
        float off = excl[c] + (wid ? wsum[c][wid - 1] : 0.f);
        sbuf[33 * t + c]      = v[c].x + off;
        sbuf[33 * t + 8 + c]  = v[c].y + off;
        sbuf[33 * t + 16 + c] = v[c].z + off;
        sbuf[33 * t + 24 + c] = v[c].w + off;
    }
    __syncthreads();

    // Coalesced float4 stores: output float index o -> smem idx = o + o/32.
    float4* out4 = (float4*)(g_sat + (size_t)y * NCOL);
    #pragma unroll
    for (int j = 0; j < 8; ++j) {
        const int o   = (j * 256 + t) * 4;
        const int idx = o + (o >> 5);
        out4[j * 256 + t] = make_float4(sbuf[idx], sbuf[idx + 1],
                                        sbuf[idx + 2], sbuf[idx + 3]);
    }
}

// ---------------------------------------------------------------------------
// Pass 2: single-pass column cumsum, decoupled lookback with early aggregate
// publish (no serial cross-segment chain). Block = 1 segment (32 rows) x 256
// columns; seg ascends with blockIdx (deps point to lower bids -> no deadlock).
// ---------------------------------------------------------------------------
__global__ void __launch_bounds__(256) colscan_kernel() {
    const int tid   = threadIdx.x;
    const int seg   = blockIdx.x >> 5;       // NCOL/256 = 32 chunks per seg
    const int chunk = blockIdx.x & 31;
    const int f     = chunk * 256 + tid;

    float* base = g_sat + (size_t)seg * SEGH * NCOL + f;

    // Local inclusive prefix over the 32 segment rows (reg-resident).
    float pref[SEGH];
    float s = 0.f;
    #pragma unroll
    for (int k = 0; k < SEGH; ++k) {
        s += __ldcg(base + (size_t)k * NCOL);
        pref[k] = s;
    }

    // Publish local aggregate immediately (flag = 1).
    if (seg < NSEG - 1) {
        unsigned long long agg =
            ((unsigned long long)__float_as_uint(s) << 32) | 1ull;
        atomicExch(&g_link[(size_t)seg * NCOL + f], agg);
    }

    // Lookback: walk predecessors, summing aggregates, stop at an inclusive.
    float off = 0.f;
    for (int i = seg - 1; i >= 0; --i) {
        unsigned long long u;
        do {
            u = atomicAdd(&g_link[(size_t)i * NCOL + f], 0ull);
        } while (!(u & 1ull));
        off += __uint_as_float((unsigned)(u >> 32));
        if (u & 2ull) break;       // that value was inclusive -> done
    }

    // Publish inclusive prefix (flag = 3).
    if (seg < NSEG - 1) {
        unsigned long long inc =
            ((unsigned long long)__float_as_uint(off + s) << 32) | 3ull;
        atomicExch(&g_link[(size_t)seg * NCOL + f], inc);
    }

    // Finalize in place.
    #pragma unroll
    for (int k = 0; k < SEGH; ++k)
        __stcg(base + (size_t)k * NCOL, pref[k] + off);
}

// ---------------------------------------------------------------------------
// Pass 3: adaptive 7x7 ROI pooling + final mean. One warp per ROI.
// g_sat holds inclusive SAT; padded sat(y,x) = g_sat[y-1][x-1] (0 at borders).
// ---------------------------------------------------------------------------
__device__ __forceinline__ void load8(int y, int x, float v[8]) {
    if (y > 0 && x > 0) {
        const float4* p = (const float4*)(g_sat + ((size_t)(y - 1) * WW + (x - 1)) * NC);
        float4 a = p[0], b = p[1];
        v[0] = a.x; v[1] = a.y; v[2] = a.z; v[3] = a.w;
        v[4] = b.x; v[5] = b.y; v[6] = b.z; v[7] = b.w;
    } else {
        #pragma unroll
        for (int c = 0; c < 8; ++c) v[c] = 0.f;
    }
}

__global__ void __launch_bounds__(256) pool_kernel(const int* __restrict__ rois,
                                                   float* __restrict__ out, int n) {
    const int warp = (blockIdx.x * blockDim.x + threadIdx.x) >> 5;
    const int lane = threadIdx.x & 31;
    if (warp >= n) return;

    // rois is int32 [n,4]
    const int4 R = ((const int4*)rois)[warp];
    const int ymin = R.x >> 5;            // // FEAT_STRIDE (=32)
    const int xmin = R.y >> 5;
    const int ymax = (R.z >> 5) + 1;      // exclusive
    const int xmax = (R.w >> 5) + 1;
    const int leny = ymax - ymin;
    const int lenx = xmax - xmin;

    float acc[8];
    #pragma unroll
    for (int c = 0; c < 8; ++c) acc[c] = 0.f;

    for (int bin = lane; bin < 49; bin += 32) {
        const int i = bin / 7;
        const int j = bin - i * 7;
        const int ylo = ymin + (i * leny) / NPOOL;
        const int yhi = ymin + ((i + 1) * leny + NPOOL - 1) / NPOOL;
        const int xlo = xmin + (j * lenx) / NPOOL;
        const int xhi = xmin + ((j + 1) * lenx + NPOOL - 1) / NPOOL;

        float Shh[8], Slh[8], Shl[8], Sll[8];
        load8(yhi, xhi, Shh);
        load8(ylo, xhi, Slh);
        load8(yhi, xlo, Shl);
        load8(ylo, xlo, Sll);

        const int   area = (yhi - ylo) * (xhi - xlo);
        const float w    = 1.f / (float)area;
        #pragma unroll
        for (int c = 0; c < 8; ++c)
            acc[c] += w * ((Shh[c] - Slh[c]) - (Shl[c] - Sll[c]));
    }

    #pragma unroll
    for (int c = 0; c < 8; ++c) {
        #pragma unroll
        for (int d = 16; d; d >>= 1)
            acc[c] += __shfl_xor_sync(0xffffffffu, acc[c], d);
    }

    if (lane == 0) {
        const float inv49 = 1.f / 49.f;
        float4 o0 = make_float4(acc[0] * inv49, acc[1] * inv49, acc[2] * inv49, acc[3] * inv49);
        float4 o1 = make_float4(acc[4] * inv49, acc[5] * inv49, acc[6] * inv49, acc[7] * inv49);
        float4* o = (float4*)(out + (size_t)warp * 8);
        o[0] = o0;
        o[1] = o1;
    }
}

// ---------------------------------------------------------------------------
extern "C" void kernel_launch(void* const* d_in, const int* in_sizes, int n_in,
                              void* d_out, int out_size) {
    const float* conv = (const float*)d_in[0];   // [8,1024,1024] fp32
    const int*   rois = (const int*)d_in[1];     // [n,4] int32
    float*       out  = (float*)d_out;           // [n,8] fp32
    const int n = in_sizes[1] / 4;

    rowscan_kernel<<<HH, 256>>>(conv);
    colscan_kernel<<<NSEG * (NCOL / 256), 256>>>();
    pool_kernel   <<<(n + 7) / 8, 256>>>(rois, out, n);
}